// round 11
// baseline (speedup 1.0000x reference)
#include <cuda_runtime.h>
#include <cuda_bf16.h>

#define N_NODES 100000
#define N_EDGES 3200000
#define IN_CH 16
#define HIDDEN 128
#define OUT_CH 16
#define N_TILES 6250           // 100000 / 16
#define CAP 128                // bin capacity per node (deg ~ Binom, mean 32)

typedef unsigned long long u64;

// ---------------- scratch (no allocation allowed) ----------------
__device__ float  g_dinv[N_NODES];
__device__ float4 g_y[N_NODES * 4];        // gather source (dinv-scaled features)
__device__ float4 g_z[N_NODES * 4];        // aggregation result
__device__ u64    g_bin[(size_t)N_NODES * CAP];   // packed (w_bits<<32 | src)
__device__ int    g_cur[N_NODES];          // fill cursor -> padded count after k_dinv_y
__device__ int    g_is32;                  // 1 if edge_index is int32

// dtype-flexible edge loads
__device__ __forceinline__ void load_edge(const void *ei, int e, int &s, int &d) {
    if (g_is32) {
        const int *p = (const int *)ei;
        s = p[e];
        d = p[e + N_EDGES];
    } else {
        const long long *p = (const long long *)ei;
        s = (int)p[e];
        d = (int)p[e + N_EDGES];
    }
}

// bf16-split helpers
__device__ __forceinline__ void split2(float x, float y, unsigned &hi, unsigned &lo) {
    __nv_bfloat162 H, L;
    H.x = __float2bfloat16(x);
    H.y = __float2bfloat16(y);
    L.x = __float2bfloat16(x - __bfloat162float(H.x));
    L.y = __float2bfloat16(y - __bfloat162float(H.y));
    hi = *reinterpret_cast<unsigned *>(&H);
    lo = *reinterpret_cast<unsigned *>(&L);
}
__device__ __forceinline__ void mma4(float c[4], const unsigned a[4],
                                     unsigned b0, unsigned b1) {
    asm volatile(
        "mma.sync.aligned.m16n8k16.row.col.f32.bf16.bf16.f32 "
        "{%0,%1,%2,%3}, {%4,%5,%6,%7}, {%8,%9}, {%0,%1,%2,%3};"
        : "+f"(c[0]), "+f"(c[1]), "+f"(c[2]), "+f"(c[3])
        : "r"(a[0]), "r"(a[1]), "r"(a[2]), "r"(a[3]), "r"(b0), "r"(b1));
}

// ---------------- kernels ----------------

// cursors = 0; block 0 does dtype detection (sample 4096 odd 32-bit words:
// int64 buffer -> high halves all zero; int32 buffer -> indices, nonzero)
__global__ void k_init(const unsigned int *__restrict__ wbuf) {
    int i = blockIdx.x * blockDim.x + threadIdx.x;
    if (i < N_NODES) g_cur[i] = 0;
    if (blockIdx.x == 0) {
        if (threadIdx.x == 0) g_is32 = 0;
        __syncthreads();
        unsigned v = 0;
        for (int k = threadIdx.x; k < 4096; k += 256) v |= wbuf[2 * k + 1];
        v = __reduce_or_sync(0xFFFFFFFFu, v);
        if ((threadIdx.x & 31) == 0 && v) atomicOr(&g_is32, 1);
    }
}

// scatter edges into per-dst bins: bin[d][pos] = (w_bits<<32 | src)
__global__ void k_scatter(const void *__restrict__ ei, const float *__restrict__ w) {
    int e = blockIdx.x * blockDim.x + threadIdx.x;
    if (e >= N_EDGES) return;
    int s, d;
    load_edge(ei, e, s, d);
    if ((unsigned)s >= N_NODES || (unsigned)d >= N_NODES) return;
    int pos = atomicAdd(&g_cur[d], 1);
    if (pos < CAP) {
        u64 p = ((u64)__float_as_uint(w[e]) << 32) | (unsigned)s;
        g_bin[(size_t)d * CAP + pos] = p;
    }
}

// warp per node: deg = 1 + sum(w); dinv = rsqrt(deg); y = x*dinv.
// Then PAD the bin row to a multiple of 32 with (w=0, src=d) entries and
// store the padded count -> k_agg runs branch-free.
__global__ void k_dinv_y(const float *__restrict__ x) {
    int warp = (blockIdx.x * blockDim.x + threadIdx.x) >> 5;
    int lane = threadIdx.x & 31;
    if (warp >= N_NODES) return;
    int d = warp;
    int n = min(g_cur[d], CAP);
    u64 *row = g_bin + (size_t)d * CAP;
    float sum = 0.0f;
    for (int i = lane; i < n; i += 32)
        sum += __uint_as_float((unsigned)(__ldg(row + i) >> 32));
#pragma unroll
    for (int o = 16; o; o >>= 1) sum += __shfl_xor_sync(0xFFFFFFFFu, sum, o);
    float deg = 1.0f + sum;
    float di = (deg > 0.0f) ? rsqrtf(deg) : 0.0f;
    // pad row to multiple of 32 with zero-weight self entries
    int padded = min(CAP, (n + 31) & ~31);
    for (int i = n + lane; i < padded; i += 32)
        row[i] = (u64)(unsigned)d;                // w_bits = 0
    if (lane == 0) {
        g_dinv[d] = di;
        g_cur[d] = padded;
    }
    if (lane < 4) {
        float4 v = ((const float4 *)x)[d * 4 + lane];
        v.x *= di; v.y *= di; v.z *= di; v.w *= di;
        g_y[d * 4 + lane] = v;
    }
}

// pull-mode aggregation, warp per node, NO atomics, branch-free inner loop.
// z[d] = y[d] + sum_e w_e * y[src_e]
// quad q = lane&3 owns channel-quad q; sub = lane>>2 owns contiguous entry
// block [base + sub*4, +4) -> two 16B bin loads + 4 unpredicated gathers.
// FINAL: write out[d] = dinv[d]*z[d] + b2 directly (fused epilogue).
template <bool FINAL>
__global__ void k_agg(const float *__restrict__ b2, float4 *__restrict__ out) {
    int warp = (blockIdx.x * blockDim.x + threadIdx.x) >> 5;
    int lane = threadIdx.x & 31;
    if (warp >= N_NODES) return;
    int d = warp, q = lane & 3, sub = lane >> 2;
    int cnt = g_cur[d];                       // multiple of 32, <= CAP
    const u64 *row = g_bin + (size_t)d * CAP;

    // self-loop seed, issued before the loop so its latency overlaps gathers
    float4 acc = make_float4(0.0f, 0.0f, 0.0f, 0.0f);
    if (sub == 0) acc = __ldg(&g_y[d * 4 + q]);

    for (int base = 0; base < cnt; base += 32) {
        const ulonglong2 *pp = (const ulonglong2 *)(row + base + sub * 4);
        ulonglong2 a = __ldg(pp);
        ulonglong2 b = __ldg(pp + 1);
        u64 p[4] = {a.x, a.y, b.x, b.y};
#pragma unroll
        for (int j = 0; j < 4; j++) {
            int s = (int)(unsigned)p[j];
            float wv = __uint_as_float((unsigned)(p[j] >> 32));
            float4 v = __ldg(&g_y[s * 4 + q]);
            acc.x += wv * v.x;
            acc.y += wv * v.y;
            acc.z += wv * v.z;
            acc.w += wv * v.w;
        }
    }
    // reduce across the 8 subs (lane bits 2..4; q preserved)
#pragma unroll
    for (int o = 4; o < 32; o <<= 1) {
        acc.x += __shfl_xor_sync(0xFFFFFFFFu, acc.x, o);
        acc.y += __shfl_xor_sync(0xFFFFFFFFu, acc.y, o);
        acc.z += __shfl_xor_sync(0xFFFFFFFFu, acc.z, o);
        acc.w += __shfl_xor_sync(0xFFFFFFFFu, acc.w, o);
    }
    if (sub == 0) {
        if (FINAL) {
            float c = g_dinv[d];
            float4 b = ((const float4 *)b2)[q];
            out[d * 4 + q] = make_float4(b.x + c * acc.x, b.y + c * acc.y,
                                         b.z + c * acc.z, b.w + c * acc.w);
        } else {
            g_z[d * 4 + q] = acc;
        }
    }
}

// ---------------- tensor-core MLP ----------------
// reads g_z: agg1 = dinv*z ; h2 = relu(agg1@W1+b1)@W2 ; writes g_y = dinv*h2
__global__ void __launch_bounds__(256) k_mlp_mma(const float *__restrict__ W1,
                                                 const float *__restrict__ b1,
                                                 const float *__restrict__ W2) {
    __shared__ uint4 fB1[16][32];       // [n-block][lane] : .xy=hi .zw=lo
    __shared__ uint4 fB2[16][32];       // [kb*2 + nb2][lane]
    __shared__ float sb1[HIDDEN];

    int t = threadIdx.x;
    for (int idx = t; idx < 512; idx += 256) {
        int nb = idx >> 5, lane = idx & 31;
        int g = lane >> 2, m = lane & 3;
        int n = nb * 8 + g;
        int k0 = 2 * m;
        uint4 f;
        unsigned hi, lo;
        split2(W1[(k0 + 0) * HIDDEN + n], W1[(k0 + 1) * HIDDEN + n], hi, lo);
        f.x = hi; f.z = lo;
        split2(W1[(k0 + 8) * HIDDEN + n], W1[(k0 + 9) * HIDDEN + n], hi, lo);
        f.y = hi; f.w = lo;
        fB1[nb][lane] = f;
    }
    for (int idx = t; idx < 512; idx += 256) {
        int kb = idx >> 6, nb2 = (idx >> 5) & 1, lane = idx & 31;
        int g = lane >> 2, m = lane & 3;
        int n = nb2 * 8 + g;
        int k0 = kb * 16 + 2 * m;
        uint4 f;
        unsigned hi, lo;
        split2(W2[(k0 + 0) * OUT_CH + n], W2[(k0 + 1) * OUT_CH + n], hi, lo);
        f.x = hi; f.z = lo;
        split2(W2[(k0 + 8) * OUT_CH + n], W2[(k0 + 9) * OUT_CH + n], hi, lo);
        f.y = hi; f.w = lo;
        fB2[kb * 2 + nb2][lane] = f;
    }
    if (t < HIDDEN) sb1[t] = b1[t];
    __syncthreads();

    int warp = (blockIdx.x * 256 + t) >> 5;
    if (warp >= N_TILES) return;
    int lane = t & 31;
    int g = lane >> 2, m = lane & 3;
    int base = warp * 16;

    int r0 = base + g, r1 = base + g + 8;
    float di0 = g_dinv[r0], di1 = g_dinv[r1];

    const float *zf = (const float *)g_z;
    float2 v0 = *(const float2 *)(zf + (size_t)r0 * 16 + 2 * m);
    float2 v1 = *(const float2 *)(zf + (size_t)r1 * 16 + 2 * m);
    float2 v2 = *(const float2 *)(zf + (size_t)r0 * 16 + 2 * m + 8);
    float2 v3 = *(const float2 *)(zf + (size_t)r1 * 16 + 2 * m + 8);
    unsigned ahi[4], alo[4];
    split2(v0.x * di0, v0.y * di0, ahi[0], alo[0]);
    split2(v1.x * di1, v1.y * di1, ahi[1], alo[1]);
    split2(v2.x * di0, v2.y * di0, ahi[2], alo[2]);
    split2(v3.x * di1, v3.y * di1, ahi[3], alo[3]);

    float d2[2][4] = {{0, 0, 0, 0}, {0, 0, 0, 0}};

#pragma unroll
    for (int kb = 0; kb < 8; kb++) {
        float c[2][4] = {{0, 0, 0, 0}, {0, 0, 0, 0}};
#pragma unroll
        for (int p = 0; p < 2; p++) {
            uint4 f = fB1[2 * kb + p][lane];
            mma4(c[p], ahi, f.x, f.y);   // Ahi*Bhi
            mma4(c[p], alo, f.x, f.y);   // Alo*Bhi
            mma4(c[p], ahi, f.z, f.w);   // Ahi*Blo
        }
#pragma unroll
        for (int p = 0; p < 2; p++) {
            float bn0 = sb1[(2 * kb + p) * 8 + 2 * m];
            float bn1 = sb1[(2 * kb + p) * 8 + 2 * m + 1];
            c[p][0] = fmaxf(c[p][0] + bn0, 0.0f);
            c[p][1] = fmaxf(c[p][1] + bn1, 0.0f);
            c[p][2] = fmaxf(c[p][2] + bn0, 0.0f);
            c[p][3] = fmaxf(c[p][3] + bn1, 0.0f);
        }
        unsigned thi[4], tlo[4];
        split2(c[0][0], c[0][1], thi[0], tlo[0]);
        split2(c[0][2], c[0][3], thi[1], tlo[1]);
        split2(c[1][0], c[1][1], thi[2], tlo[2]);
        split2(c[1][2], c[1][3], thi[3], tlo[3]);
#pragma unroll
        for (int q = 0; q < 2; q++) {
            uint4 f = fB2[kb * 2 + q][lane];
            mma4(d2[q], thi, f.x, f.y);
            mma4(d2[q], tlo, f.x, f.y);
            mma4(d2[q], thi, f.z, f.w);
        }
    }

    // y2 = dinv * h2 -> g_y (gather source + self-loop seed for pass B)
    float *yf = (float *)g_y;
    *(float2 *)(yf + (size_t)r0 * 16 + 2 * m)     = make_float2(d2[0][0] * di0, d2[0][1] * di0);
    *(float2 *)(yf + (size_t)r1 * 16 + 2 * m)     = make_float2(d2[0][2] * di1, d2[0][3] * di1);
    *(float2 *)(yf + (size_t)r0 * 16 + 8 + 2 * m) = make_float2(d2[1][0] * di0, d2[1][1] * di0);
    *(float2 *)(yf + (size_t)r1 * 16 + 8 + 2 * m) = make_float2(d2[1][2] * di1, d2[1][3] * di1);
}

// ---------------- launch ----------------
extern "C" void kernel_launch(void *const *d_in, const int *in_sizes, int n_in,
                              void *d_out, int out_size) {
    const float *x = 0, *w = 0, *W1 = 0, *b1 = 0, *W2 = 0, *b2 = 0;
    const void *ei = 0;
    for (int i = 0; i < n_in; i++) {
        switch (in_sizes[i]) {
            case N_NODES * IN_CH:  x = (const float *)d_in[i]; break;
            case 2 * N_EDGES:      ei = d_in[i]; break;
            case N_EDGES:          w = (const float *)d_in[i]; break;
            case IN_CH * HIDDEN:   if (!W1) W1 = (const float *)d_in[i];
                                   else     W2 = (const float *)d_in[i]; break;
            case HIDDEN:           b1 = (const float *)d_in[i]; break;
            case OUT_CH:           b2 = (const float *)d_in[i]; break;
        }
    }
    float4 *out = (float4 *)d_out;

    const int nbN  = (N_NODES + 255) / 256;
    const int nbE  = (N_EDGES + 255) / 256;
    const int nbWN = (N_NODES * 32 + 255) / 256;   // warp per node
    const int nbW  = (N_TILES * 32 + 255) / 256;   // warp per 16-node tile

    k_init<<<nbN, 256>>>((const unsigned int *)ei);
    k_scatter<<<nbE, 256>>>(ei, w);                  // build bins (once)
    k_dinv_y<<<nbWN, 256>>>(x);                      // deg/dinv + y + row padding
    k_agg<false><<<nbWN, 256>>>(b2, out);            // z = y + sum w*y[src]
    k_mlp_mma<<<nbW, 256>>>(W1, b1, W2);             // y = dinv*MLP(dinv*z)
    k_agg<true><<<nbWN, 256>>>(b2, out);             // out = dinv*(...) + b2
}

// round 12
// speedup vs baseline: 1.3956x; 1.3956x over previous
#include <cuda_runtime.h>
#include <cuda_bf16.h>

#define N_NODES 100000
#define N_EDGES 3200000
#define IN_CH 16
#define HIDDEN 128
#define OUT_CH 16
#define N_TILES 6250           // 100000 / 16
#define CAP 128                // bin capacity per node (deg ~ Binom, mean 32)

typedef unsigned long long u64;

// ---------------- scratch (no allocation allowed) ----------------
__device__ float  g_dinv[N_NODES];
__device__ float4 g_y[N_NODES * 4];        // gather source (dinv-scaled features)
__device__ float4 g_z[N_NODES * 4];        // aggregation result
__device__ u64    g_bin[(size_t)N_NODES * CAP];   // packed (w_bits<<32 | src)
__device__ int    g_cur[N_NODES];          // per-node fill cursor (== in-degree)
__device__ int    g_is32;                  // 1 if edge_index is int32

// dtype-flexible edge loads
__device__ __forceinline__ void load_edge(const void *ei, int e, int &s, int &d) {
    if (g_is32) {
        const int *p = (const int *)ei;
        s = p[e];
        d = p[e + N_EDGES];
    } else {
        const long long *p = (const long long *)ei;
        s = (int)p[e];
        d = (int)p[e + N_EDGES];
    }
}

// bf16-split helpers
__device__ __forceinline__ void split2(float x, float y, unsigned &hi, unsigned &lo) {
    __nv_bfloat162 H, L;
    H.x = __float2bfloat16(x);
    H.y = __float2bfloat16(y);
    L.x = __float2bfloat16(x - __bfloat162float(H.x));
    L.y = __float2bfloat16(y - __bfloat162float(H.y));
    hi = *reinterpret_cast<unsigned *>(&H);
    lo = *reinterpret_cast<unsigned *>(&L);
}
__device__ __forceinline__ void mma4(float c[4], const unsigned a[4],
                                     unsigned b0, unsigned b1) {
    asm volatile(
        "mma.sync.aligned.m16n8k16.row.col.f32.bf16.bf16.f32 "
        "{%0,%1,%2,%3}, {%4,%5,%6,%7}, {%8,%9}, {%0,%1,%2,%3};"
        : "+f"(c[0]), "+f"(c[1]), "+f"(c[2]), "+f"(c[3])
        : "r"(a[0]), "r"(a[1]), "r"(a[2]), "r"(a[3]), "r"(b0), "r"(b1));
}

// ---------------- kernels ----------------

// cursors = 0; block 0 does dtype detection (sample 4096 odd 32-bit words:
// int64 buffer -> high halves all zero; int32 buffer -> indices, nonzero)
__global__ void k_init(const unsigned int *__restrict__ wbuf) {
    int i = blockIdx.x * blockDim.x + threadIdx.x;
    if (i < N_NODES) g_cur[i] = 0;
    if (blockIdx.x == 0) {
        if (threadIdx.x == 0) g_is32 = 0;
        __syncthreads();
        unsigned v = 0;
        for (int k = threadIdx.x; k < 4096; k += 256) v |= wbuf[2 * k + 1];
        v = __reduce_or_sync(0xFFFFFFFFu, v);
        if ((threadIdx.x & 31) == 0 && v) atomicOr(&g_is32, 1);
    }
}

// scatter edges into per-dst bins: bin[d][pos] = (w_bits<<32 | src)
__global__ void k_scatter(const void *__restrict__ ei, const float *__restrict__ w) {
    int e = blockIdx.x * blockDim.x + threadIdx.x;
    if (e >= N_EDGES) return;
    int s, d;
    load_edge(ei, e, s, d);
    if ((unsigned)s >= N_NODES || (unsigned)d >= N_NODES) return;
    int pos = atomicAdd(&g_cur[d], 1);
    if (pos < CAP) {
        u64 p = ((u64)__float_as_uint(w[e]) << 32) | (unsigned)s;
        g_bin[(size_t)d * CAP + pos] = p;
    }
}

// warp per node: deg = 1 + sum(w over bin row); dinv = rsqrt(deg); y = x*dinv.
// First 32 bin entries are loaded SPECULATIVELY (addresses depend only on the
// warp id), masked by (i < n); removes the cnt->bin dependency from the chain.
__global__ void k_dinv_y(const float *__restrict__ x) {
    int warp = (blockIdx.x * blockDim.x + threadIdx.x) >> 5;
    int lane = threadIdx.x & 31;
    if (warp >= N_NODES) return;
    int d = warp;
    const u64 *row = g_bin + (size_t)d * CAP;
    u64 p0 = __ldg(row + lane);                 // speculative
    int n = min(g_cur[d], CAP);                 // parallel with p0
    float sum = (lane < n) ? __uint_as_float((unsigned)(p0 >> 32)) : 0.0f;
    for (int i = 32 + lane; i < n; i += 32)
        sum += __uint_as_float((unsigned)(__ldg(row + i) >> 32));
#pragma unroll
    for (int o = 16; o; o >>= 1) sum += __shfl_xor_sync(0xFFFFFFFFu, sum, o);
    float deg = 1.0f + sum;
    float di = (deg > 0.0f) ? rsqrtf(deg) : 0.0f;
    if (lane == 0) g_dinv[d] = di;
    if (lane < 4) {
        float4 v = ((const float4 *)x)[d * 4 + lane];
        v.x *= di; v.y *= di; v.z *= di; v.w *= di;
        g_y[d * 4 + lane] = v;
    }
}

// pull-mode aggregation, warp per node, NO atomics.
// z[d] = y[d] + sum_e w_e * y[src_e]
// quad q = lane&3 owns channel-quad q; sub = lane>>2 strides edges by 8.
// First batch (entries 0..31) is SPECULATIVE: bin loads issue before cnt
// arrives; garbage entries are neutralized by wv=0 + unsigned index clamp.
// FINAL: write out[d] = dinv[d]*z[d] + b2 directly (fused epilogue).
template <bool FINAL>
__global__ void k_agg(const float *__restrict__ b2, float4 *__restrict__ out) {
    int warp = (blockIdx.x * blockDim.x + threadIdx.x) >> 5;
    int lane = threadIdx.x & 31;
    if (warp >= N_NODES) return;
    int d = warp, q = lane & 3, sub = lane >> 2;
    const u64 *row = g_bin + (size_t)d * CAP;

    // speculative first-batch bin loads (no dependency on cnt)
    u64 p0[4];
#pragma unroll
    for (int j = 0; j < 4; j++) p0[j] = __ldg(row + sub + j * 8);

    int n = min(g_cur[d], CAP);                 // issued in parallel

    // self-loop seed
    float4 acc = make_float4(0.0f, 0.0f, 0.0f, 0.0f);
    if (sub == 0) acc = __ldg(&g_y[d * 4 + q]);

    // first batch: clamp index, zero weight beyond n (gather is safe + masked)
#pragma unroll
    for (int j = 0; j < 4; j++) {
        unsigned s = min((unsigned)p0[j], (unsigned)(N_NODES - 1));
        float wv = (sub + j * 8 < n)
                       ? __uint_as_float((unsigned)(p0[j] >> 32)) : 0.0f;
        float4 v = __ldg(&g_y[s * 4 + q]);
        acc.x += wv * v.x;
        acc.y += wv * v.y;
        acc.z += wv * v.z;
        acc.w += wv * v.w;
    }

    // remaining batches (rare: deg > 32), R10-style predicated unroll-4
    for (int it0 = 32 + sub; it0 < n; it0 += 32) {
        u64 p[4];
#pragma unroll
        for (int j = 0; j < 4; j++) {
            int it = it0 + j * 8;
            p[j] = (it < n) ? __ldg(row + it) : 0;
        }
#pragma unroll
        for (int j = 0; j < 4; j++) {
            if (it0 + j * 8 < n) {
                int s = (int)(unsigned)p[j];
                float wv = __uint_as_float((unsigned)(p[j] >> 32));
                float4 v = __ldg(&g_y[s * 4 + q]);
                acc.x += wv * v.x;
                acc.y += wv * v.y;
                acc.z += wv * v.z;
                acc.w += wv * v.w;
            }
        }
    }
    // reduce across the 8 edge-groups (lane bits 2..4; q preserved)
#pragma unroll
    for (int o = 4; o < 32; o <<= 1) {
        acc.x += __shfl_xor_sync(0xFFFFFFFFu, acc.x, o);
        acc.y += __shfl_xor_sync(0xFFFFFFFFu, acc.y, o);
        acc.z += __shfl_xor_sync(0xFFFFFFFFu, acc.z, o);
        acc.w += __shfl_xor_sync(0xFFFFFFFFu, acc.w, o);
    }
    if (sub == 0) {
        if (FINAL) {
            float c = g_dinv[d];
            float4 b = ((const float4 *)b2)[q];
            out[d * 4 + q] = make_float4(b.x + c * acc.x, b.y + c * acc.y,
                                         b.z + c * acc.z, b.w + c * acc.w);
        } else {
            g_z[d * 4 + q] = acc;
        }
    }
}

// ---------------- tensor-core MLP ----------------
// reads g_z: agg1 = dinv*z ; h2 = relu(agg1@W1+b1)@W2 ; writes g_y = dinv*h2
__global__ void __launch_bounds__(256) k_mlp_mma(const float *__restrict__ W1,
                                                 const float *__restrict__ b1,
                                                 const float *__restrict__ W2) {
    __shared__ uint4 fB1[16][32];       // [n-block][lane] : .xy=hi .zw=lo
    __shared__ uint4 fB2[16][32];       // [kb*2 + nb2][lane]
    __shared__ float sb1[HIDDEN];

    int t = threadIdx.x;
    for (int idx = t; idx < 512; idx += 256) {
        int nb = idx >> 5, lane = idx & 31;
        int g = lane >> 2, m = lane & 3;
        int n = nb * 8 + g;
        int k0 = 2 * m;
        uint4 f;
        unsigned hi, lo;
        split2(W1[(k0 + 0) * HIDDEN + n], W1[(k0 + 1) * HIDDEN + n], hi, lo);
        f.x = hi; f.z = lo;
        split2(W1[(k0 + 8) * HIDDEN + n], W1[(k0 + 9) * HIDDEN + n], hi, lo);
        f.y = hi; f.w = lo;
        fB1[nb][lane] = f;
    }
    for (int idx = t; idx < 512; idx += 256) {
        int kb = idx >> 6, nb2 = (idx >> 5) & 1, lane = idx & 31;
        int g = lane >> 2, m = lane & 3;
        int n = nb2 * 8 + g;
        int k0 = kb * 16 + 2 * m;
        uint4 f;
        unsigned hi, lo;
        split2(W2[(k0 + 0) * OUT_CH + n], W2[(k0 + 1) * OUT_CH + n], hi, lo);
        f.x = hi; f.z = lo;
        split2(W2[(k0 + 8) * OUT_CH + n], W2[(k0 + 9) * OUT_CH + n], hi, lo);
        f.y = hi; f.w = lo;
        fB2[kb * 2 + nb2][lane] = f;
    }
    if (t < HIDDEN) sb1[t] = b1[t];
    __syncthreads();

    int warp = (blockIdx.x * 256 + t) >> 5;
    if (warp >= N_TILES) return;
    int lane = t & 31;
    int g = lane >> 2, m = lane & 3;
    int base = warp * 16;

    int r0 = base + g, r1 = base + g + 8;
    float di0 = g_dinv[r0], di1 = g_dinv[r1];

    const float *zf = (const float *)g_z;
    float2 v0 = *(const float2 *)(zf + (size_t)r0 * 16 + 2 * m);
    float2 v1 = *(const float2 *)(zf + (size_t)r1 * 16 + 2 * m);
    float2 v2 = *(const float2 *)(zf + (size_t)r0 * 16 + 2 * m + 8);
    float2 v3 = *(const float2 *)(zf + (size_t)r1 * 16 + 2 * m + 8);
    unsigned ahi[4], alo[4];
    split2(v0.x * di0, v0.y * di0, ahi[0], alo[0]);
    split2(v1.x * di1, v1.y * di1, ahi[1], alo[1]);
    split2(v2.x * di0, v2.y * di0, ahi[2], alo[2]);
    split2(v3.x * di1, v3.y * di1, ahi[3], alo[3]);

    float d2[2][4] = {{0, 0, 0, 0}, {0, 0, 0, 0}};

#pragma unroll
    for (int kb = 0; kb < 8; kb++) {
        float c[2][4] = {{0, 0, 0, 0}, {0, 0, 0, 0}};
#pragma unroll
        for (int p = 0; p < 2; p++) {
            uint4 f = fB1[2 * kb + p][lane];
            mma4(c[p], ahi, f.x, f.y);   // Ahi*Bhi
            mma4(c[p], alo, f.x, f.y);   // Alo*Bhi
            mma4(c[p], ahi, f.z, f.w);   // Ahi*Blo
        }
#pragma unroll
        for (int p = 0; p < 2; p++) {
            float bn0 = sb1[(2 * kb + p) * 8 + 2 * m];
            float bn1 = sb1[(2 * kb + p) * 8 + 2 * m + 1];
            c[p][0] = fmaxf(c[p][0] + bn0, 0.0f);
            c[p][1] = fmaxf(c[p][1] + bn1, 0.0f);
            c[p][2] = fmaxf(c[p][2] + bn0, 0.0f);
            c[p][3] = fmaxf(c[p][3] + bn1, 0.0f);
        }
        unsigned thi[4], tlo[4];
        split2(c[0][0], c[0][1], thi[0], tlo[0]);
        split2(c[0][2], c[0][3], thi[1], tlo[1]);
        split2(c[1][0], c[1][1], thi[2], tlo[2]);
        split2(c[1][2], c[1][3], thi[3], tlo[3]);
#pragma unroll
        for (int q = 0; q < 2; q++) {
            uint4 f = fB2[kb * 2 + q][lane];
            mma4(d2[q], thi, f.x, f.y);
            mma4(d2[q], tlo, f.x, f.y);
            mma4(d2[q], thi, f.z, f.w);
        }
    }

    // y2 = dinv * h2 -> g_y (gather source + self-loop seed for pass B)
    float *yf = (float *)g_y;
    *(float2 *)(yf + (size_t)r0 * 16 + 2 * m)     = make_float2(d2[0][0] * di0, d2[0][1] * di0);
    *(float2 *)(yf + (size_t)r1 * 16 + 2 * m)     = make_float2(d2[0][2] * di1, d2[0][3] * di1);
    *(float2 *)(yf + (size_t)r0 * 16 + 8 + 2 * m) = make_float2(d2[1][0] * di0, d2[1][1] * di0);
    *(float2 *)(yf + (size_t)r1 * 16 + 8 + 2 * m) = make_float2(d2[1][2] * di1, d2[1][3] * di1);
}

// ---------------- launch ----------------
extern "C" void kernel_launch(void *const *d_in, const int *in_sizes, int n_in,
                              void *d_out, int out_size) {
    const float *x = 0, *w = 0, *W1 = 0, *b1 = 0, *W2 = 0, *b2 = 0;
    const void *ei = 0;
    for (int i = 0; i < n_in; i++) {
        switch (in_sizes[i]) {
            case N_NODES * IN_CH:  x = (const float *)d_in[i]; break;
            case 2 * N_EDGES:      ei = d_in[i]; break;
            case N_EDGES:          w = (const float *)d_in[i]; break;
            case IN_CH * HIDDEN:   if (!W1) W1 = (const float *)d_in[i];
                                   else     W2 = (const float *)d_in[i]; break;
            case HIDDEN:           b1 = (const float *)d_in[i]; break;
            case OUT_CH:           b2 = (const float *)d_in[i]; break;
        }
    }
    float4 *out = (float4 *)d_out;

    const int nbN  = (N_NODES + 255) / 256;
    const int nbE  = (N_EDGES + 255) / 256;
    const int nbWN = (N_NODES * 32 + 255) / 256;   // warp per node
    const int nbW  = (N_TILES * 32 + 255) / 256;   // warp per 16-node tile

    k_init<<<nbN, 256>>>((const unsigned int *)ei);
    k_scatter<<<nbE, 256>>>(ei, w);                  // build bins (once)
    k_dinv_y<<<nbWN, 256>>>(x);                      // deg/dinv + y = x*dinv
    k_agg<false><<<nbWN, 256>>>(b2, out);            // z = y + sum w*y[src]
    k_mlp_mma<<<nbW, 256>>>(W1, b1, W2);             // y = dinv*MLP(dinv*z)
    k_agg<true><<<nbWN, 256>>>(b2, out);             // out = dinv*(...) + b2
}

// round 14
// speedup vs baseline: 1.4846x; 1.0638x over previous
#include <cuda_runtime.h>
#include <cuda_bf16.h>

#define N_NODES 100000
#define N_EDGES 3200000
#define IN_CH 16
#define HIDDEN 128
#define OUT_CH 16
#define N_TILES 6250           // 100000 / 16
#define CAP 128                // bin capacity per node (deg ~ Binom, mean 32)

typedef unsigned long long u64;

// ---------------- scratch (no allocation allowed) ----------------
__device__ float  g_dinv[N_NODES];
__device__ float4 g_y[N_NODES * 4];        // gather source (dinv-scaled features)
__device__ float4 g_z[N_NODES * 4];        // aggregation result
__device__ u64    g_bin[(size_t)N_NODES * CAP];   // packed (w_bits<<32 | src)
__device__ int    g_cur[N_NODES];          // per-node fill cursor (== in-degree)
__device__ int    g_is32;                  // 1 if edge_index is int32

// bf16-split helpers
__device__ __forceinline__ void split2(float x, float y, unsigned &hi, unsigned &lo) {
    __nv_bfloat162 H, L;
    H.x = __float2bfloat16(x);
    H.y = __float2bfloat16(y);
    L.x = __float2bfloat16(x - __bfloat162float(H.x));
    L.y = __float2bfloat16(y - __bfloat162float(H.y));
    hi = *reinterpret_cast<unsigned *>(&H);
    lo = *reinterpret_cast<unsigned *>(&L);
}
__device__ __forceinline__ void mma4(float c[4], const unsigned a[4],
                                     unsigned b0, unsigned b1) {
    asm volatile(
        "mma.sync.aligned.m16n8k16.row.col.f32.bf16.bf16.f32 "
        "{%0,%1,%2,%3}, {%4,%5,%6,%7}, {%8,%9}, {%0,%1,%2,%3};"
        : "+f"(c[0]), "+f"(c[1]), "+f"(c[2]), "+f"(c[3])
        : "r"(a[0]), "r"(a[1]), "r"(a[2]), "r"(a[3]), "r"(b0), "r"(b1));
}

// ---------------- kernels ----------------

// cursors = 0; block 0 does dtype detection (sample 4096 odd 32-bit words:
// int64 buffer -> high halves all zero; int32 buffer -> indices, nonzero)
__global__ void k_init(const unsigned int *__restrict__ wbuf) {
    int i = blockIdx.x * blockDim.x + threadIdx.x;
    if (i < N_NODES) g_cur[i] = 0;
    if (blockIdx.x == 0) {
        if (threadIdx.x == 0) g_is32 = 0;
        __syncthreads();
        unsigned v = 0;
        for (int k = threadIdx.x; k < 4096; k += 256) v |= wbuf[2 * k + 1];
        v = __reduce_or_sync(0xFFFFFFFFu, v);
        if ((threadIdx.x & 31) == 0 && v) atomicOr(&g_is32, 1);
    }
}

// scatter edges into per-dst bins, 4 edges per thread.
// Vector loads for indices + weights, then 4 INDEPENDENT atomic->store
// chains in flight (the single-edge version is ILP=1 on a ~600cyc chain).
__global__ void k_scatter4(const void *__restrict__ ei, const float *__restrict__ w) {
    int t = blockIdx.x * blockDim.x + threadIdx.x;
    int e0 = t * 4;
    if (e0 >= N_EDGES) return;           // N_EDGES % 4 == 0 -> full quads only

    int s[4], d[4];
    if (g_is32) {
        const int4 *ps = (const int4 *)((const int *)ei + e0);
        const int4 *pd = (const int4 *)((const int *)ei + N_EDGES + e0);
        int4 sv = __ldg(ps), dv = __ldg(pd);
        s[0] = sv.x; s[1] = sv.y; s[2] = sv.z; s[3] = sv.w;
        d[0] = dv.x; d[1] = dv.y; d[2] = dv.z; d[3] = dv.w;
    } else {
        const longlong2 *ps = (const longlong2 *)((const long long *)ei + e0);
        const longlong2 *pd = (const longlong2 *)((const long long *)ei + N_EDGES + e0);
        longlong2 s01 = __ldg(ps), s23 = __ldg(ps + 1);
        longlong2 d01 = __ldg(pd), d23 = __ldg(pd + 1);
        s[0] = (int)s01.x; s[1] = (int)s01.y; s[2] = (int)s23.x; s[3] = (int)s23.y;
        d[0] = (int)d01.x; d[1] = (int)d01.y; d[2] = (int)d23.x; d[3] = (int)d23.y;
    }
    float4 wv = __ldg((const float4 *)(w + e0));
    float wa[4] = {wv.x, wv.y, wv.z, wv.w};

    int pos[4];
    bool ok[4];
#pragma unroll
    for (int j = 0; j < 4; j++) {
        ok[j] = ((unsigned)s[j] < N_NODES) && ((unsigned)d[j] < N_NODES);
        pos[j] = ok[j] ? atomicAdd(&g_cur[d[j]], 1) : CAP;   // 4 chains in flight
    }
#pragma unroll
    for (int j = 0; j < 4; j++) {
        if (ok[j] && pos[j] < CAP) {
            u64 p = ((u64)__float_as_uint(wa[j]) << 32) | (unsigned)s[j];
            g_bin[(size_t)d[j] * CAP + pos[j]] = p;
        }
    }
}

// warp per node: deg = 1 + sum(w over bin row); dinv = rsqrt(deg); y = x*dinv
__global__ void k_dinv_y(const float *__restrict__ x) {
    int warp = (blockIdx.x * blockDim.x + threadIdx.x) >> 5;
    int lane = threadIdx.x & 31;
    if (warp >= N_NODES) return;
    int d = warp;
    int n = min(g_cur[d], CAP);
    const u64 *row = g_bin + (size_t)d * CAP;
    float sum = 0.0f;
    for (int i = lane; i < n; i += 32)
        sum += __uint_as_float((unsigned)(__ldg(row + i) >> 32));
#pragma unroll
    for (int o = 16; o; o >>= 1) sum += __shfl_xor_sync(0xFFFFFFFFu, sum, o);
    float deg = 1.0f + sum;
    float di = (deg > 0.0f) ? rsqrtf(deg) : 0.0f;
    if (lane == 0) g_dinv[d] = di;
    if (lane < 4) {
        float4 v = ((const float4 *)x)[d * 4 + lane];
        v.x *= di; v.y *= di; v.z *= di; v.w *= di;
        g_y[d * 4 + lane] = v;
    }
}

// pull-mode aggregation, warp per node, NO atomics (R10 form — known best).
// z[d] = y[d] + sum_e w_e * y[src_e]
// quad q = lane&3 owns channel-quad q; sub = lane>>2 strides edges by 8.
// Unroll-by-4 batches 4 independent bin loads + 4 independent gathers.
// FINAL: write out[d] = dinv[d]*z[d] + b2 directly (fused epilogue).
template <bool FINAL>
__global__ void k_agg(const float *__restrict__ b2, float4 *__restrict__ out) {
    int warp = (blockIdx.x * blockDim.x + threadIdx.x) >> 5;
    int lane = threadIdx.x & 31;
    if (warp >= N_NODES) return;
    int d = warp, q = lane & 3, sub = lane >> 2;
    int n = min(g_cur[d], CAP);
    const u64 *row = g_bin + (size_t)d * CAP;

    // self-loop seed, issued before the loop so its latency overlaps gathers
    float4 acc = make_float4(0.0f, 0.0f, 0.0f, 0.0f);
    if (sub == 0) acc = __ldg(&g_y[d * 4 + q]);

    for (int it0 = sub; it0 < n; it0 += 32) {
        u64 p[4];
#pragma unroll
        for (int j = 0; j < 4; j++) {
            int it = it0 + j * 8;
            p[j] = (it < n) ? __ldg(row + it) : 0;
        }
#pragma unroll
        for (int j = 0; j < 4; j++) {
            if (it0 + j * 8 < n) {
                int s = (int)(unsigned)p[j];
                float wv = __uint_as_float((unsigned)(p[j] >> 32));
                float4 v = __ldg(&g_y[s * 4 + q]);
                acc.x += wv * v.x;
                acc.y += wv * v.y;
                acc.z += wv * v.z;
                acc.w += wv * v.w;
            }
        }
    }
    // reduce across the 8 edge-groups (lane bits 2..4; q preserved)
#pragma unroll
    for (int o = 4; o < 32; o <<= 1) {
        acc.x += __shfl_xor_sync(0xFFFFFFFFu, acc.x, o);
        acc.y += __shfl_xor_sync(0xFFFFFFFFu, acc.y, o);
        acc.z += __shfl_xor_sync(0xFFFFFFFFu, acc.z, o);
        acc.w += __shfl_xor_sync(0xFFFFFFFFu, acc.w, o);
    }
    if (sub == 0) {
        if (FINAL) {
            float c = g_dinv[d];
            float4 b = ((const float4 *)b2)[q];
            out[d * 4 + q] = make_float4(b.x + c * acc.x, b.y + c * acc.y,
                                         b.z + c * acc.z, b.w + c * acc.w);
        } else {
            g_z[d * 4 + q] = acc;
        }
    }
}

// ---------------- tensor-core MLP ----------------
// reads g_z: agg1 = dinv*z ; h2 = relu(agg1@W1+b1)@W2 ; writes g_y = dinv*h2
__global__ void __launch_bounds__(256) k_mlp_mma(const float *__restrict__ W1,
                                                 const float *__restrict__ b1,
                                                 const float *__restrict__ W2) {
    __shared__ uint4 fB1[16][32];       // [n-block][lane] : .xy=hi .zw=lo
    __shared__ uint4 fB2[16][32];       // [kb*2 + nb2][lane]
    __shared__ float sb1[HIDDEN];

    int t = threadIdx.x;
    for (int idx = t; idx < 512; idx += 256) {
        int nb = idx >> 5, lane = idx & 31;
        int g = lane >> 2, m = lane & 3;
        int n = nb * 8 + g;
        int k0 = 2 * m;
        uint4 f;
        unsigned hi, lo;
        split2(W1[(k0 + 0) * HIDDEN + n], W1[(k0 + 1) * HIDDEN + n], hi, lo);
        f.x = hi; f.z = lo;
        split2(W1[(k0 + 8) * HIDDEN + n], W1[(k0 + 9) * HIDDEN + n], hi, lo);
        f.y = hi; f.w = lo;
        fB1[nb][lane] = f;
    }
    for (int idx = t; idx < 512; idx += 256) {
        int kb = idx >> 6, nb2 = (idx >> 5) & 1, lane = idx & 31;
        int g = lane >> 2, m = lane & 3;
        int n = nb2 * 8 + g;
        int k0 = kb * 16 + 2 * m;
        uint4 f;
        unsigned hi, lo;
        split2(W2[(k0 + 0) * OUT_CH + n], W2[(k0 + 1) * OUT_CH + n], hi, lo);
        f.x = hi; f.z = lo;
        split2(W2[(k0 + 8) * OUT_CH + n], W2[(k0 + 9) * OUT_CH + n], hi, lo);
        f.y = hi; f.w = lo;
        fB2[kb * 2 + nb2][lane] = f;
    }
    if (t < HIDDEN) sb1[t] = b1[t];
    __syncthreads();

    int warp = (blockIdx.x * 256 + t) >> 5;
    if (warp >= N_TILES) return;
    int lane = t & 31;
    int g = lane >> 2, m = lane & 3;
    int base = warp * 16;

    int r0 = base + g, r1 = base + g + 8;
    float di0 = g_dinv[r0], di1 = g_dinv[r1];

    const float *zf = (const float *)g_z;
    float2 v0 = *(const float2 *)(zf + (size_t)r0 * 16 + 2 * m);
    float2 v1 = *(const float2 *)(zf + (size_t)r1 * 16 + 2 * m);
    float2 v2 = *(const float2 *)(zf + (size_t)r0 * 16 + 2 * m + 8);
    float2 v3 = *(const float2 *)(zf + (size_t)r1 * 16 + 2 * m + 8);
    unsigned ahi[4], alo[4];
    split2(v0.x * di0, v0.y * di0, ahi[0], alo[0]);
    split2(v1.x * di1, v1.y * di1, ahi[1], alo[1]);
    split2(v2.x * di0, v2.y * di0, ahi[2], alo[2]);
    split2(v3.x * di1, v3.y * di1, ahi[3], alo[3]);

    float d2[2][4] = {{0, 0, 0, 0}, {0, 0, 0, 0}};

#pragma unroll
    for (int kb = 0; kb < 8; kb++) {
        float c[2][4] = {{0, 0, 0, 0}, {0, 0, 0, 0}};
#pragma unroll
        for (int p = 0; p < 2; p++) {
            uint4 f = fB1[2 * kb + p][lane];
            mma4(c[p], ahi, f.x, f.y);   // Ahi*Bhi
            mma4(c[p], alo, f.x, f.y);   // Alo*Bhi
            mma4(c[p], ahi, f.z, f.w);   // Ahi*Blo
        }
#pragma unroll
        for (int p = 0; p < 2; p++) {
            float bn0 = sb1[(2 * kb + p) * 8 + 2 * m];
            float bn1 = sb1[(2 * kb + p) * 8 + 2 * m + 1];
            c[p][0] = fmaxf(c[p][0] + bn0, 0.0f);
            c[p][1] = fmaxf(c[p][1] + bn1, 0.0f);
            c[p][2] = fmaxf(c[p][2] + bn0, 0.0f);
            c[p][3] = fmaxf(c[p][3] + bn1, 0.0f);
        }
        unsigned thi[4], tlo[4];
        split2(c[0][0], c[0][1], thi[0], tlo[0]);
        split2(c[0][2], c[0][3], thi[1], tlo[1]);
        split2(c[1][0], c[1][1], thi[2], tlo[2]);
        split2(c[1][2], c[1][3], thi[3], tlo[3]);
#pragma unroll
        for (int q = 0; q < 2; q++) {
            uint4 f = fB2[kb * 2 + q][lane];
            mma4(d2[q], thi, f.x, f.y);
            mma4(d2[q], tlo, f.x, f.y);
            mma4(d2[q], thi, f.z, f.w);
        }
    }

    // y2 = dinv * h2 -> g_y (gather source + self-loop seed for pass B)
    float *yf = (float *)g_y;
    *(float2 *)(yf + (size_t)r0 * 16 + 2 * m)     = make_float2(d2[0][0] * di0, d2[0][1] * di0);
    *(float2 *)(yf + (size_t)r1 * 16 + 2 * m)     = make_float2(d2[0][2] * di1, d2[0][3] * di1);
    *(float2 *)(yf + (size_t)r0 * 16 + 8 + 2 * m) = make_float2(d2[1][0] * di0, d2[1][1] * di0);
    *(float2 *)(yf + (size_t)r1 * 16 + 8 + 2 * m) = make_float2(d2[1][2] * di1, d2[1][3] * di1);
}

// ---------------- launch ----------------
extern "C" void kernel_launch(void *const *d_in, const int *in_sizes, int n_in,
                              void *d_out, int out_size) {
    const float *x = 0, *w = 0, *W1 = 0, *b1 = 0, *W2 = 0, *b2 = 0;
    const void *ei = 0;
    for (int i = 0; i < n_in; i++) {
        switch (in_sizes[i]) {
            case N_NODES * IN_CH:  x = (const float *)d_in[i]; break;
            case 2 * N_EDGES:      ei = d_in[i]; break;
            case N_EDGES:          w = (const float *)d_in[i]; break;
            case IN_CH * HIDDEN:   if (!W1) W1 = (const float *)d_in[i];
                                   else     W2 = (const float *)d_in[i]; break;
            case HIDDEN:           b1 = (const float *)d_in[i]; break;
            case OUT_CH:           b2 = (const float *)d_in[i]; break;
        }
    }
    float4 *out = (float4 *)d_out;

    const int nbN  = (N_NODES + 255) / 256;
    const int nbE4 = (N_EDGES / 4 + 255) / 256;    // 4 edges per thread
    const int nbWN = (N_NODES * 32 + 255) / 256;   // warp per node
    const int nbW  = (N_TILES * 32 + 255) / 256;   // warp per 16-node tile

    k_init<<<nbN, 256>>>((const unsigned int *)ei);
    k_scatter4<<<nbE4, 256>>>(ei, w);                // build bins (once)
    k_dinv_y<<<nbWN, 256>>>(x);                      // deg/dinv + y = x*dinv
    k_agg<false><<<nbWN, 256>>>(b2, out);            // z = y + sum w*y[src]
    k_mlp_mma<<<nbW, 256>>>(W1, b1, W2);             // y = dinv*MLP(dinv*z)
    k_agg<true><<<nbWN, 256>>>(b2, out);             // out = dinv*(...) + b2
}